// round 1
// baseline (speedup 1.0000x reference)
#include <cuda_runtime.h>

#define BB 4
#define NN 8192
#define CC 64
#define OUTD 64
#define KNNK 36
#define BN (BB*NN)
#define KBLK 128

// Device scratch (allocation-free rule: __device__ globals)
__device__ float4 g_xyz4[BN];            // (sq, x, y, z) packed per point
__device__ float  g_vfeat[BN*OUTD];      // relu([feature,xyz] @ W_v + b_v)
__device__ int    g_knn[BN*KNNK];        // top-36 neighbor indices (unsorted)

// ---------------------------------------------------------------------------
// Pack xyz into float4 with squared norm (for fast distance: sq_j - 2*dot)
// ---------------------------------------------------------------------------
__global__ void pack_xyz_kernel(const float* __restrict__ xyz) {
    int i = blockIdx.x * blockDim.x + threadIdx.x;
    if (i >= BN) return;
    float x = xyz[3*i], y = xyz[3*i+1], z = xyz[3*i+2];
    g_xyz4[i] = make_float4(x*x + y*y + z*z, x, y, z);
}

// ---------------------------------------------------------------------------
// v_feat = relu(concat([feature, xyz]) @ W_v + b_v)   (B,N,64)
// 256 threads = 4 points x 64 out-channels
// ---------------------------------------------------------------------------
__global__ __launch_bounds__(256) void vfeat_kernel(
    const float* __restrict__ feature,
    const float* __restrict__ xyz,
    const float* __restrict__ Wv,
    const float* __restrict__ bv)
{
    __shared__ float fsh[4][68];
    int sub = threadIdx.x >> 6;        // 0..3
    int t   = threadIdx.x & 63;        // out channel
    int p   = blockIdx.x * 4 + sub;    // point index
    fsh[sub][t] = feature[p*64 + t];
    if (t < 3) fsh[sub][64 + t] = xyz[p*3 + t];
    __syncthreads();
    const float* f = fsh[sub];
    float acc = bv[t];
    #pragma unroll
    for (int c = 0; c < 67; c++)
        acc = fmaf(f[c], Wv[c*64 + t], acc);
    g_vfeat[p*64 + t] = fmaxf(acc, 0.0f);
}

// ---------------------------------------------------------------------------
// Exact 36-NN: thread-per-query brute force over all 8192 candidates.
// Distance metric: dist3 = sq_j - 2*dot(q, c)  (== full dist - sq_q, same order)
// Top-36 kept in local-mem arrays, replace-max + unrolled rescan.
// ---------------------------------------------------------------------------
__global__ __launch_bounds__(KBLK) void knn_kernel() {
    __shared__ float4 tile[KBLK];
    int q = blockIdx.x * KBLK + threadIdx.x;   // global query point
    int b = q >> 13;                           // batch (N = 8192 = 2^13)

    float4 me = g_xyz4[q];
    float nx = -2.0f * me.y, ny = -2.0f * me.z, nz = -2.0f * me.w;

    float dcur[KNNK];
    int   icur[KNNK];
    #pragma unroll
    for (int s = 0; s < KNNK; s++) { dcur[s] = 3.4e38f; icur[s] = 0; }
    float worst = 3.4e38f;
    int   wpos  = 0;

    const float4* __restrict__ cand = g_xyz4 + b * NN;

    for (int base = 0; base < NN; base += KBLK) {
        __syncthreads();
        tile[threadIdx.x] = cand[base + threadIdx.x];
        __syncthreads();
        #pragma unroll 4
        for (int j = 0; j < KBLK; j++) {
            float4 c = tile[j];
            float d = fmaf(nx, c.y, c.x);
            d = fmaf(ny, c.z, d);
            d = fmaf(nz, c.w, d);
            if (d < worst) {
                dcur[wpos] = d;
                icur[wpos] = base + j;
                float w2 = -3.4e38f; int p2 = 0;
                #pragma unroll
                for (int s = 0; s < KNNK; s++)
                    if (dcur[s] > w2) { w2 = dcur[s]; p2 = s; }
                worst = w2; wpos = p2;
            }
        }
    }
    #pragma unroll
    for (int s = 0; s < KNNK; s++)
        g_knn[q*KNNK + s] = icur[s];
}

// ---------------------------------------------------------------------------
// Attention + suffix GEMM. Warp per point, 8 points per 256-thread block.
// w_k = dot(feature[nbr_k], feature[q]); softmax over k;
// o = sum_k w_k * v_feat[nbr_k]; out = o @ W_suf + b_suf
// Lane l owns channels {2l, 2l+1}. K=36 weights: lane l holds wA (k=l) and
// lanes 0..3 additionally hold wB (k=32+l).
// ---------------------------------------------------------------------------
__global__ __launch_bounds__(256) void attn_kernel(
    const float* __restrict__ feature,
    const float* __restrict__ Wsuf,
    const float* __restrict__ bsuf,
    float* __restrict__ out)
{
    __shared__ float osh[8][64];
    const unsigned FULL = 0xffffffffu;
    int w    = threadIdx.x >> 5;
    int lane = threadIdx.x & 31;
    int p    = blockIdx.x * 8 + w;
    int b    = p >> 13;

    const float* frow = feature + (size_t)p * 64;
    float2 q2 = *(const float2*)(frow + 2*lane);

    int idxA = g_knn[p*KNNK + lane];
    int idxB = (lane < 4) ? g_knn[p*KNNK + 32 + lane] : 0;

    const float* fbase = feature + (size_t)b * NN * 64;
    float wA = 0.0f, wB = -3.4e38f;

    // raw attention logits
    #pragma unroll
    for (int k = 0; k < KNNK; k++) {
        int j = (k < 32) ? __shfl_sync(FULL, idxA, k)
                         : __shfl_sync(FULL, idxB, k - 32);
        float2 f2 = *(const float2*)(fbase + (size_t)j * 64 + 2*lane);
        float part = fmaf(f2.x, q2.x, f2.y * q2.y);
        #pragma unroll
        for (int s = 16; s; s >>= 1)
            part += __shfl_xor_sync(FULL, part, s);
        if (k < 32) { if (lane == k)      wA = part; }
        else        { if (lane == k - 32) wB = part; }
    }

    // softmax over 36 (lanes >= 4 mask wB out)
    float m = fmaxf(wA, (lane < 4) ? wB : -3.4e38f);
    #pragma unroll
    for (int s = 16; s; s >>= 1)
        m = fmaxf(m, __shfl_xor_sync(FULL, m, s));
    float eA = __expf(wA - m);
    float eB = (lane < 4) ? __expf(wB - m) : 0.0f;
    float ssum = eA + eB;
    #pragma unroll
    for (int s = 16; s; s >>= 1)
        ssum += __shfl_xor_sync(FULL, ssum, s);
    float inv = 1.0f / ssum;
    eA *= inv; eB *= inv;

    // weighted sum of v_feat over neighbors
    const float* vbase = g_vfeat + (size_t)b * NN * 64;
    float ox = 0.0f, oy = 0.0f;
    #pragma unroll
    for (int k = 0; k < KNNK; k++) {
        int j; float wk;
        if (k < 32) { j = __shfl_sync(FULL, idxA, k);      wk = __shfl_sync(FULL, eA, k); }
        else        { j = __shfl_sync(FULL, idxB, k - 32); wk = __shfl_sync(FULL, eB, k - 32); }
        float2 v2 = *(const float2*)(vbase + (size_t)j * 64 + 2*lane);
        ox = fmaf(wk, v2.x, ox);
        oy = fmaf(wk, v2.y, oy);
    }

    // suffix linear: out = o @ W_suf + b_suf
    osh[w][2*lane]     = ox;
    osh[w][2*lane + 1] = oy;
    __syncwarp();
    float2 acc = *(const float2*)(bsuf + 2*lane);
    #pragma unroll 8
    for (int c = 0; c < 64; c++) {
        float oc = osh[w][c];
        float2 wv = *(const float2*)(Wsuf + c*64 + 2*lane);
        acc.x = fmaf(oc, wv.x, acc.x);
        acc.y = fmaf(oc, wv.y, acc.y);
    }
    *(float2*)(out + (size_t)p * 64 + 2*lane) = acc;
}

// Fill any trailing output elements (the reference returns (out, N))
__global__ void tail_kernel(float* __restrict__ out, int out_size) {
    int i = BN*OUTD + blockIdx.x * blockDim.x + threadIdx.x;
    if (i < out_size) out[i] = (float)NN;
}

extern "C" void kernel_launch(void* const* d_in, const int* in_sizes, int n_in,
                              void* d_out, int out_size) {
    const float* feature = (const float*)d_in[0];
    const float* xyz     = (const float*)d_in[1];
    const float* Wv      = (const float*)d_in[2];
    const float* bv      = (const float*)d_in[3];
    const float* Wsuf    = (const float*)d_in[4];
    const float* bsuf    = (const float*)d_in[5];
    float* out = (float*)d_out;

    pack_xyz_kernel<<<(BN + 255) / 256, 256>>>(xyz);
    vfeat_kernel<<<BN / 4, 256>>>(feature, xyz, Wv, bv);
    knn_kernel<<<BN / KBLK, KBLK>>>();
    attn_kernel<<<BN / 8, 256>>>(feature, Wsuf, bsuf, out);

    if (out_size > BN*OUTD) {
        int extra = out_size - BN*OUTD;
        tail_kernel<<<(extra + 255) / 256, 256>>>(out, out_size);
    }
}

// round 2
// speedup vs baseline: 1.6498x; 1.6498x over previous
#include <cuda_runtime.h>

#define BB 4
#define NN 8192
#define CC 64
#define OUTD 64
#define KNNK 36
#define BN (BB*NN)
#define KBLK 128
#define BUFCAP 40      // per-thread smem buffer slots
#define FLUSH_AT 8     // flush when any lane has more than this buffered

// Device scratch (allocation-free rule: __device__ globals)
__device__ float4 g_xyz4[BN];            // (sq, x, y, z) packed per point
__device__ float  g_vfeat[BN*OUTD];      // relu([feature,xyz] @ W_v + b_v)
__device__ int    g_knn[BN*KNNK];        // top-36 neighbor indices (unsorted)

// ---------------------------------------------------------------------------
// Pack xyz into float4 with squared norm (for fast distance: sq_j - 2*dot)
// ---------------------------------------------------------------------------
__global__ void pack_xyz_kernel(const float* __restrict__ xyz) {
    int i = blockIdx.x * blockDim.x + threadIdx.x;
    if (i >= BN) return;
    float x = xyz[3*i], y = xyz[3*i+1], z = xyz[3*i+2];
    g_xyz4[i] = make_float4(x*x + y*y + z*z, x, y, z);
}

// ---------------------------------------------------------------------------
// v_feat = relu(concat([feature, xyz]) @ W_v + b_v)   (B,N,64)
// ---------------------------------------------------------------------------
__global__ __launch_bounds__(256) void vfeat_kernel(
    const float* __restrict__ feature,
    const float* __restrict__ xyz,
    const float* __restrict__ Wv,
    const float* __restrict__ bv)
{
    __shared__ float fsh[4][68];
    int sub = threadIdx.x >> 6;
    int t   = threadIdx.x & 63;
    int p   = blockIdx.x * 4 + sub;
    fsh[sub][t] = feature[p*64 + t];
    if (t < 3) fsh[sub][64 + t] = xyz[p*3 + t];
    __syncthreads();
    const float* f = fsh[sub];
    float acc = bv[t];
    #pragma unroll
    for (int c = 0; c < 67; c++)
        acc = fmaf(f[c], Wv[c*64 + t], acc);
    g_vfeat[p*64 + t] = fmaxf(acc, 0.0f);
}

// ---------------------------------------------------------------------------
// Exact 36-NN with buffered selection.
// Thread per query. Per candidate: 1 LDS.128 (broadcast) + 3 FMA + predicated
// push into a per-thread smem buffer (no branch, no BSSY). Every 32 candidates
// a warp-uniform __any_sync decides whether ALL lanes flush their buffers into
// the local-memory top-36 (replace-max + rescan). This amortizes the expensive
// divergent rescans from ~3400/warp down to ~dozens/warp.
// ---------------------------------------------------------------------------
struct TopK {
    float d[KNNK];
    int   i[KNNK];
};

__device__ __forceinline__ void flush_buf(
    int& cnt, int tid, TopK& tk, float& worst, int& wpos,
    const float* __restrict__ bufd, const int* __restrict__ bufi)
{
    for (int it = 0; it < cnt; it++) {
        float d = bufd[it*KBLK + tid];
        if (d < worst) {
            tk.d[wpos] = d;
            tk.i[wpos] = bufi[it*KBLK + tid];
            float w2 = -3.4e38f; int p2 = 0;
            #pragma unroll
            for (int s = 0; s < KNNK; s++)
                if (tk.d[s] > w2) { w2 = tk.d[s]; p2 = s; }
            worst = w2; wpos = p2;
        }
    }
    cnt = 0;
}

__global__ __launch_bounds__(KBLK) void knn_kernel() {
    __shared__ float4 tile[KBLK];
    __shared__ float  bufd[BUFCAP*KBLK];
    __shared__ int    bufi[BUFCAP*KBLK];
    const unsigned FULL = 0xffffffffu;

    int tid = threadIdx.x;
    int q = blockIdx.x * KBLK + tid;
    int b = q >> 13;

    float4 me = g_xyz4[q];
    float nx = -2.0f * me.y, ny = -2.0f * me.z, nz = -2.0f * me.w;

    TopK tk;
    #pragma unroll
    for (int s = 0; s < KNNK; s++) { tk.d[s] = 3.4e38f; tk.i[s] = 0; }
    float worst = 3.4e38f;
    int   wpos  = 0;
    int   cnt   = 0;

    const float4* __restrict__ cand = g_xyz4 + b * NN;

    for (int base = 0; base < NN; base += KBLK) {
        __syncthreads();
        tile[tid] = cand[base + tid];
        __syncthreads();
        #pragma unroll
        for (int js = 0; js < KBLK; js += 32) {
            #pragma unroll
            for (int jj = 0; jj < 32; jj++) {
                float4 c = tile[js + jj];
                float d = fmaf(nx, c.y, c.x);
                d = fmaf(ny, c.z, d);
                d = fmaf(nz, c.w, d);
                if (d < worst) {                 // predicated push
                    bufd[cnt*KBLK + tid] = d;
                    bufi[cnt*KBLK + tid] = base + js + jj;
                    cnt++;
                }
            }
            if (__any_sync(FULL, cnt > FLUSH_AT))
                flush_buf(cnt, tid, tk, worst, wpos, bufd, bufi);
        }
    }
    flush_buf(cnt, tid, tk, worst, wpos, bufd, bufi);

    #pragma unroll
    for (int s = 0; s < KNNK; s++)
        g_knn[q*KNNK + s] = tk.i[s];
}

// ---------------------------------------------------------------------------
// Attention + suffix GEMM. Warp per point, 8 points per 256-thread block.
// ---------------------------------------------------------------------------
__global__ __launch_bounds__(256) void attn_kernel(
    const float* __restrict__ feature,
    const float* __restrict__ Wsuf,
    const float* __restrict__ bsuf,
    float* __restrict__ out)
{
    __shared__ float osh[8][64];
    const unsigned FULL = 0xffffffffu;
    int w    = threadIdx.x >> 5;
    int lane = threadIdx.x & 31;
    int p    = blockIdx.x * 8 + w;
    int b    = p >> 13;

    const float* frow = feature + (size_t)p * 64;
    float2 q2 = *(const float2*)(frow + 2*lane);

    int idxA = g_knn[p*KNNK + lane];
    int idxB = (lane < 4) ? g_knn[p*KNNK + 32 + lane] : 0;

    const float* fbase = feature + (size_t)b * NN * 64;
    float wA = 0.0f, wB = -3.4e38f;

    #pragma unroll
    for (int k = 0; k < KNNK; k++) {
        int j = (k < 32) ? __shfl_sync(FULL, idxA, k)
                         : __shfl_sync(FULL, idxB, k - 32);
        float2 f2 = *(const float2*)(fbase + (size_t)j * 64 + 2*lane);
        float part = fmaf(f2.x, q2.x, f2.y * q2.y);
        #pragma unroll
        for (int s = 16; s; s >>= 1)
            part += __shfl_xor_sync(FULL, part, s);
        if (k < 32) { if (lane == k)      wA = part; }
        else        { if (lane == k - 32) wB = part; }
    }

    float m = fmaxf(wA, (lane < 4) ? wB : -3.4e38f);
    #pragma unroll
    for (int s = 16; s; s >>= 1)
        m = fmaxf(m, __shfl_xor_sync(FULL, m, s));
    float eA = __expf(wA - m);
    float eB = (lane < 4) ? __expf(wB - m) : 0.0f;
    float ssum = eA + eB;
    #pragma unroll
    for (int s = 16; s; s >>= 1)
        ssum += __shfl_xor_sync(FULL, ssum, s);
    float inv = 1.0f / ssum;
    eA *= inv; eB *= inv;

    const float* vbase = g_vfeat + (size_t)b * NN * 64;
    float ox = 0.0f, oy = 0.0f;
    #pragma unroll
    for (int k = 0; k < KNNK; k++) {
        int j; float wk;
        if (k < 32) { j = __shfl_sync(FULL, idxA, k);      wk = __shfl_sync(FULL, eA, k); }
        else        { j = __shfl_sync(FULL, idxB, k - 32); wk = __shfl_sync(FULL, eB, k - 32); }
        float2 v2 = *(const float2*)(vbase + (size_t)j * 64 + 2*lane);
        ox = fmaf(wk, v2.x, ox);
        oy = fmaf(wk, v2.y, oy);
    }

    osh[w][2*lane]     = ox;
    osh[w][2*lane + 1] = oy;
    __syncwarp();
    float2 acc = *(const float2*)(bsuf + 2*lane);
    #pragma unroll 8
    for (int c = 0; c < 64; c++) {
        float oc = osh[w][c];
        float2 wv = *(const float2*)(Wsuf + c*64 + 2*lane);
        acc.x = fmaf(oc, wv.x, acc.x);
        acc.y = fmaf(oc, wv.y, acc.y);
    }
    *(float2*)(out + (size_t)p * 64 + 2*lane) = acc;
}

__global__ void tail_kernel(float* __restrict__ out, int out_size) {
    int i = BN*OUTD + blockIdx.x * blockDim.x + threadIdx.x;
    if (i < out_size) out[i] = (float)NN;
}

extern "C" void kernel_launch(void* const* d_in, const int* in_sizes, int n_in,
                              void* d_out, int out_size) {
    const float* feature = (const float*)d_in[0];
    const float* xyz     = (const float*)d_in[1];
    const float* Wv      = (const float*)d_in[2];
    const float* bv      = (const float*)d_in[3];
    const float* Wsuf    = (const float*)d_in[4];
    const float* bsuf    = (const float*)d_in[5];
    float* out = (float*)d_out;

    pack_xyz_kernel<<<(BN + 255) / 256, 256>>>(xyz);
    vfeat_kernel<<<BN / 4, 256>>>(feature, xyz, Wv, bv);
    knn_kernel<<<BN / KBLK, KBLK>>>();
    attn_kernel<<<BN / 8, 256>>>(feature, Wsuf, bsuf, out);

    if (out_size > BN*OUTD) {
        int extra = out_size - BN*OUTD;
        tail_kernel<<<(extra + 255) / 256, 256>>>(out, out_size);
    }
}